// round 2
// baseline (speedup 1.0000x reference)
#include <cuda_runtime.h>
#include <cstdint>
#include <math.h>

// ---------------- problem constants ----------------
#define INV_TAU (1.0f / 0.07f)
constexpr int Bb = 16, Ll = 32, Dd = 256, Kk = 131072;
constexpr int Nn = 512;          // B*L frames
constexpr int NQ = 528;          // 512 z rows + 16 g rows
constexpr int NQP = 576;         // padded to 9*64
constexpr int BM = 64, BN = 128, BK = 32;
constexpr int NTILES = Kk / BN;  // 1024
constexpr int MTILES = NQP / BM; // 9
constexpr int MLL = Bb * (Ll - 1);  // 496 anchors

// ---------------- device scratch (no allocations allowed) ----------------
__device__ float d_Qbuf[NQP * Dd];          // prescaled queries (z/TAU, g/TAU, 0-pad)
__device__ float d_part[NQP * NTILES];      // partial lse per (row, n-tile)
__device__ float d_lseq[NQ];                // lse over queue per query row
__device__ float d_llterms[MLL];
__device__ float d_glterms[Nn];

// ---------------- helpers ----------------
__device__ __forceinline__ uint32_t f2tf(float x) {
    uint32_t r;
    asm("cvt.rna.tf32.f32 %0, %1;" : "=r"(r) : "f"(x));
    return r;
}

__device__ __forceinline__ void mma8(float4& d, const uint32_t* a, const uint32_t* b) {
    asm volatile(
        "mma.sync.aligned.m16n8k8.row.col.f32.tf32.tf32.f32 "
        "{%0,%1,%2,%3}, {%4,%5,%6,%7}, {%8,%9}, {%0,%1,%2,%3};\n"
        : "+f"(d.x), "+f"(d.y), "+f"(d.z), "+f"(d.w)
        : "r"(a[0]), "r"(a[1]), "r"(a[2]), "r"(a[3]), "r"(b[0]), "r"(b[1]));
}

// stable softplus-style: logaddexp(p, l) - p = softplus(l - p)
__device__ __forceinline__ float softplusf(float x) {
    return (x > 0.f) ? x + log1pf(expf(-x)) : log1pf(expf(x));
}

// ---------------- kernel 1: build prescaled query buffer ----------------
__global__ void k_prep(const float* __restrict__ z, const float* __restrict__ g) {
    int i = blockIdx.x * blockDim.x + threadIdx.x;   // 0 .. NQP*Dd-1
    int row = i >> 8, d = i & 255;
    float v = 0.f;
    if (row < Nn)       v = z[i] * INV_TAU;
    else if (row < NQ)  v = g[(row - Nn) * Dd + d] * INV_TAU;
    d_Qbuf[i] = v;
}

// ---------------- kernel 2: tf32 GEMM vs queue + per-tile lse ----------------
__global__ __launch_bounds__(256) void k_gemm(const float* __restrict__ mq) {
    __shared__ uint32_t As[BM][BK + 4];    // pitch 36: conflict-free frag reads
    __shared__ uint32_t Bs[BN][BK + 4];
    __shared__ float red_m[BM][4];
    __shared__ float red_s[BM][4];

    const int tid   = threadIdx.x;
    const int mtile = blockIdx.x;
    const int ntile = blockIdx.y;
    const int warp  = tid >> 5, lane = tid & 31;
    const int wm = warp >> 2, wn = warp & 3;     // 2 x 4 warp grid
    const int g8 = lane >> 2, tg = lane & 3;

    float4 acc[2][4];
#pragma unroll
    for (int mi = 0; mi < 2; mi++)
#pragma unroll
        for (int ni = 0; ni < 4; ni++)
            acc[mi][ni] = make_float4(0.f, 0.f, 0.f, 0.f);

    const float* Qb = d_Qbuf + mtile * BM * Dd;
    const float* Mb = mq + (long)ntile * BN * Dd;

    for (int kk = 0; kk < Dd; kk += BK) {
        // A tile 64x32 (2 float4 / thread)
#pragma unroll
        for (int i = 0; i < 2; i++) {
            int id = tid + i * 256;
            int r = id >> 3, c4 = id & 7;
            float4 v = *(const float4*)(Qb + r * Dd + kk + c4 * 4);
            uint4 u = make_uint4(f2tf(v.x), f2tf(v.y), f2tf(v.z), f2tf(v.w));
            *(uint4*)&As[r][c4 * 4] = u;
        }
        // B tile 128x32 (4 float4 / thread)
#pragma unroll
        for (int i = 0; i < 4; i++) {
            int id = tid + i * 256;
            int r = id >> 3, c4 = id & 7;
            float4 v = *(const float4*)(Mb + r * Dd + kk + c4 * 4);
            uint4 u = make_uint4(f2tf(v.x), f2tf(v.y), f2tf(v.z), f2tf(v.w));
            *(uint4*)&Bs[r][c4 * 4] = u;
        }
        __syncthreads();

#pragma unroll
        for (int ks = 0; ks < 4; ks++) {
            const int k0 = ks * 8;
            uint32_t a[2][4];
#pragma unroll
            for (int mi = 0; mi < 2; mi++) {
                int r = wm * 32 + mi * 16 + g8;
                a[mi][0] = As[r][k0 + tg];
                a[mi][1] = As[r + 8][k0 + tg];
                a[mi][2] = As[r][k0 + tg + 4];
                a[mi][3] = As[r + 8][k0 + tg + 4];
            }
            uint32_t b[4][2];
#pragma unroll
            for (int ni = 0; ni < 4; ni++) {
                int c = wn * 32 + ni * 8 + g8;
                b[ni][0] = Bs[c][k0 + tg];
                b[ni][1] = Bs[c][k0 + tg + 4];
            }
#pragma unroll
            for (int mi = 0; mi < 2; mi++)
#pragma unroll
                for (int ni = 0; ni < 4; ni++)
                    mma8(acc[mi][ni], a[mi], b[ni]);
        }
        __syncthreads();
    }

    // ---- epilogue: per-row (max, sumexp) over this 128-col tile ----
#pragma unroll
    for (int mi = 0; mi < 2; mi++) {
#pragma unroll
        for (int half = 0; half < 2; half++) {
            float v[8];
#pragma unroll
            for (int ni = 0; ni < 4; ni++) {
                v[2 * ni]     = half ? acc[mi][ni].z : acc[mi][ni].x;
                v[2 * ni + 1] = half ? acc[mi][ni].w : acc[mi][ni].y;
            }
            float m = v[0];
#pragma unroll
            for (int i = 1; i < 8; i++) m = fmaxf(m, v[i]);
            float s = 0.f;
#pragma unroll
            for (int i = 0; i < 8; i++) s += expf(v[i] - m);
            // reduce across the 4 lanes sharing this row (lanes differ in tg)
#pragma unroll
            for (int o = 1; o < 4; o <<= 1) {
                float om = __shfl_xor_sync(0xffffffffu, m, o);
                float os = __shfl_xor_sync(0xffffffffu, s, o);
                float nm = fmaxf(m, om);
                s = s * expf(m - nm) + os * expf(om - nm);
                m = nm;
            }
            if (tg == 0) {
                int rl = wm * 32 + mi * 16 + half * 8 + g8;
                red_m[rl][wn] = m;
                red_s[rl][wn] = s;
            }
        }
    }
    __syncthreads();

    if (tid < BM) {
        float m = red_m[tid][0], s = red_s[tid][0];
#pragma unroll
        for (int w = 1; w < 4; w++) {
            float om = red_m[tid][w], os = red_s[tid][w];
            float nm = fmaxf(m, om);
            s = s * expf(m - nm) + os * expf(om - nm);
            m = nm;
        }
        int grow = mtile * BM + tid;
        if (grow < NQ) d_part[grow * NTILES + ntile] = m + logf(s);
    }
}

// ---------------- kernel 3: reduce 1024 partial lse -> lse_q per row ----------------
__global__ void k_reduce() {
    const int row = blockIdx.x, tid = threadIdx.x;
    const float* p = d_part + row * NTILES;
    float vals[4];
    float m = -INFINITY;
#pragma unroll
    for (int i = 0; i < 4; i++) {
        vals[i] = p[tid + i * 256];
        m = fmaxf(m, vals[i]);
    }
    __shared__ float sm[256];
    sm[tid] = m;
    __syncthreads();
    for (int st = 128; st; st >>= 1) {
        if (tid < st) sm[tid] = fmaxf(sm[tid], sm[tid + st]);
        __syncthreads();
    }
    const float M = sm[0];
    __syncthreads();
    float s = 0.f;
#pragma unroll
    for (int i = 0; i < 4; i++) s += expf(vals[i] - M);
    sm[tid] = s;
    __syncthreads();
    for (int st = 128; st; st >>= 1) {
        if (tid < st) sm[tid] += sm[tid + st];
        __syncthreads();
    }
    if (tid == 0) d_lseq[row] = M + logf(sm[0]);
}

// ---------------- kernel 4: fp32 row losses (z@z.T and g@z.T parts) ----------------
__global__ void k_rows(const float* __restrict__ z) {
    __shared__ float qs[Dd];
    __shared__ float rm[256], rs[256];
    __shared__ float posbuf[Ll];
    __shared__ float s_pos;
    __shared__ float s_lse;

    const int bid = blockIdx.x, tid = threadIdx.x;
    const bool is_g = (bid >= Nn);
    const int a = bid;            // z frame index when !is_g
    const int gb = bid - Nn;      // g index when is_g

    qs[tid] = d_Qbuf[bid * Dd + tid];   // already divided by TAU
    __syncthreads();

    float m = -INFINITY, sacc = 0.f;
#pragma unroll
    for (int rep = 0; rep < 2; rep++) {
        const int j = tid + rep * 256;
        const float4* q4 = (const float4*)qs;
        const float4* z4 = (const float4*)(z + j * Dd);
        float d0 = 0.f, d1 = 0.f;
#pragma unroll 8
        for (int d = 0; d < 64; d += 2) {
            float4 aq = q4[d], bz = z4[d];
            d0 += aq.x * bz.x + aq.y * bz.y + aq.z * bz.z + aq.w * bz.w;
            float4 aq2 = q4[d + 1], bz2 = z4[d + 1];
            d1 += aq2.x * bz2.x + aq2.y * bz2.y + aq2.z * bz2.z + aq2.w * bz2.w;
        }
        const float v = d0 + d1;  // sim / TAU
        bool masked = false;
        if (is_g) {
            if ((j >> 5) == gb) { posbuf[j & 31] = v; masked = true; }
        } else {
            if (j == a) masked = true;
            else if (j == a + 1) { s_pos = v; masked = true; }
        }
        if (!masked) {
            if (v > m) { sacc = sacc * expf(m - v) + 1.f; m = v; }
            else       { sacc += expf(v - m); }
        }
    }

    rm[tid] = m; rs[tid] = sacc;
    __syncthreads();
    for (int st = 128; st; st >>= 1) {
        if (tid < st) {
            float m1 = rm[tid], s1 = rs[tid];
            float m2 = rm[tid + st], s2 = rs[tid + st];
            float nm = fmaxf(m1, m2);
            float ns;
            if (nm == -INFINITY) ns = 0.f;
            else ns = s1 * expf(m1 - nm) + s2 * expf(m2 - nm);
            rm[tid] = nm; rs[tid] = ns;
        }
        __syncthreads();
    }
    if (tid == 0) {
        const float lneg = rm[0] + logf(rs[0]);
        const float lq = d_lseq[bid];
        const float hi = fmaxf(lneg, lq), lo = fminf(lneg, lq);
        s_lse = hi + log1pf(expf(lo - hi));
    }
    __syncthreads();

    if (!is_g) {
        const int t = a & (Ll - 1);
        if (t < Ll - 1 && tid == 0) {
            d_llterms[(a >> 5) * (Ll - 1) + t] = softplusf(s_lse - s_pos);
        }
    } else {
        if (tid < Ll) {
            d_glterms[gb * Ll + tid] = softplusf(s_lse - posbuf[tid]);
        }
    }
}

// ---------------- kernel 5: deterministic final reduction ----------------
__global__ void k_final(const float* __restrict__ z, float* __restrict__ out) {
    __shared__ float sm[256];
    const int tid = threadIdx.x;

    float sll = 0.f;
    for (int i = tid; i < MLL; i += 256) sll += d_llterms[i];
    float sgl = 0.f;
    for (int i = tid; i < Nn; i += 256) sgl += d_glterms[i];
    float ssm = 0.f;
    const int total = Bb * (Ll - 1) * Dd;
    for (int i = tid; i < total; i += 256) {
        int b = i / ((Ll - 1) * Dd);
        int r = i % ((Ll - 1) * Dd);
        int t = r >> 8, d = r & 255;
        float df = z[(b * Ll + t + 1) * Dd + d] - z[(b * Ll + t) * Dd + d];
        ssm += df * df;
    }

    float Sll, Sgl, Ssm;
    sm[tid] = sll; __syncthreads();
    for (int st = 128; st; st >>= 1) { if (tid < st) sm[tid] += sm[tid + st]; __syncthreads(); }
    Sll = sm[0]; __syncthreads();
    sm[tid] = sgl; __syncthreads();
    for (int st = 128; st; st >>= 1) { if (tid < st) sm[tid] += sm[tid + st]; __syncthreads(); }
    Sgl = sm[0]; __syncthreads();
    sm[tid] = ssm; __syncthreads();
    for (int st = 128; st; st >>= 1) { if (tid < st) sm[tid] += sm[tid + st]; __syncthreads(); }
    Ssm = sm[0];

    if (tid == 0) {
        out[0] = Sll / (float)MLL + 0.5f * (Sgl / (float)Nn) + 0.1f * (Ssm / (float)MLL);
    }
}

// ---------------- launch ----------------
extern "C" void kernel_launch(void* const* d_in, const int* in_sizes, int n_in,
                              void* d_out, int out_size) {
    const float* z  = (const float*)d_in[0];   // z_t  [16,32,256]
    const float* g  = (const float*)d_in[1];   // g    [16,256]
    const float* mq = (const float*)d_in[3];   // memory_queue [131072,256]
    float* out = (float*)d_out;

    k_prep<<<NQP, 256>>>(z, g);
    dim3 grid(MTILES, NTILES);     // row-tiles fastest -> queue chunk L2 reuse
    k_gemm<<<grid, 256>>>(mq);
    k_reduce<<<NQ, 256>>>();
    k_rows<<<NQ, 256>>>(z);
    k_final<<<1, 256>>>(z, out);
}

// round 3
// speedup vs baseline: 1.3533x; 1.3533x over previous
#include <cuda_runtime.h>
#include <cstdint>
#include <math.h>

// ---------------- problem constants ----------------
#define INV_TAU (1.0f / 0.07f)
constexpr int Bb = 16, Ll = 32, Dd = 256, Kk = 131072;
constexpr int Nn = 512;          // B*L frames
constexpr int NQ = 528;          // 512 z rows + 16 g rows
constexpr int NQP = 576;         // padded to 3*192
constexpr int BM = 192, BN = 128, BK = 32;
constexpr int NT_Q = Kk / BN;    // 1024 queue tiles
constexpr int NT_Z = Nn / BN;    // 4 z-key tiles
constexpr int NT = NT_Q + NT_Z;  // 1028
constexpr int MT = NQP / BM;     // 3
constexpr int MLL = Bb * (Ll - 1);

// smem layout (floats), pitch 36 for conflict-free frag reads
constexpr int AP = 36;
constexpr int A_ST = BM * AP;            // 6912 per stage
constexpr int B_ST = BN * AP;            // 4608 per stage
constexpr int OFF_A0 = 0, OFF_A1 = A_ST;
constexpr int OFF_B0 = 2 * A_ST, OFF_B1 = 2 * A_ST + B_ST;
constexpr int OFF_RM = 2 * A_ST + 2 * B_ST;        // 192*2
constexpr int OFF_RS = OFF_RM + BM * 2;
constexpr int SMEM_FLOATS = OFF_RS + BM * 2;       // 23808
constexpr int SMEM_BYTES = SMEM_FLOATS * 4;        // 95232

// ---------------- device scratch ----------------
__device__ float d_Qbuf[NQP * Dd];
__device__ float d_part[NQP * NT_Q];
__device__ float d_lseq[NQ];
__device__ float d_Sim[NQP * Nn];     // 576 x 512 raw sims (already /TAU)
__device__ float d_llterms[MLL];
__device__ float d_glterms[Nn];

// ---------------- helpers ----------------
__device__ __forceinline__ uint32_t f2tf(float x) {
    uint32_t r;
    asm("cvt.rna.tf32.f32 %0, %1;" : "=r"(r) : "f"(x));
    return r;
}
__device__ __forceinline__ void mma8(float4& d, const uint32_t* a, const uint32_t* b) {
    asm volatile(
        "mma.sync.aligned.m16n8k8.row.col.f32.tf32.tf32.f32 "
        "{%0,%1,%2,%3}, {%4,%5,%6,%7}, {%8,%9}, {%0,%1,%2,%3};\n"
        : "+f"(d.x), "+f"(d.y), "+f"(d.z), "+f"(d.w)
        : "r"(a[0]), "r"(a[1]), "r"(a[2]), "r"(a[3]), "r"(b[0]), "r"(b[1]));
}
__device__ __forceinline__ void cpasync16(uint32_t dst, const float* src) {
    asm volatile("cp.async.cg.shared.global [%0], [%1], 16;\n" :: "r"(dst), "l"(src));
}
__device__ __forceinline__ float softplusf(float x) {
    return (x > 0.f) ? x + log1pf(expf(-x)) : log1pf(expf(x));
}

// ---------------- kernel 1: build prescaled (and tf32-rounded) query buffer ----------------
__global__ void k_prep(const float* __restrict__ z, const float* __restrict__ g) {
    int i = blockIdx.x * blockDim.x + threadIdx.x;
    int row = i >> 8, d = i & 255;
    float v = 0.f;
    if (row < Nn)       v = z[i] * INV_TAU;
    else if (row < NQ)  v = g[(row - Nn) * Dd + d] * INV_TAU;
    d_Qbuf[i] = __uint_as_float(f2tf(v));
}

// ---------------- kernel 2: pipelined tf32 GEMM (queries x [queue; z]) ----------------
__global__ __launch_bounds__(256, 1) void k_gemm(const float* __restrict__ mq,
                                                 const float* __restrict__ zk) {
    extern __shared__ float smem[];
    const uint32_t smem_u32 = (uint32_t)__cvta_generic_to_shared(smem);

    const int tid  = threadIdx.x;
    const int warp = tid >> 5, lane = tid & 31;
    const int wm = warp >> 1, wn = warp & 1;   // 4 x 2 warp grid
    const int g8 = lane >> 2, tg = lane & 3;
    const int mtile = blockIdx.x;
    const int ntile = blockIdx.y;
    const bool is_z = (ntile >= NT_Q);

    const float* Qb = d_Qbuf + mtile * BM * Dd;
    const float* Kb = is_z ? (zk + (size_t)(ntile - NT_Q) * BN * Dd)
                           : (mq + (size_t)ntile * BN * Dd);

    // per-thread load indices (8 float4-cols per 32-float row)
    float4 acc[3][8];
#pragma unroll
    for (int mi = 0; mi < 3; mi++)
#pragma unroll
        for (int ni = 0; ni < 8; ni++) acc[mi][ni] = make_float4(0.f, 0.f, 0.f, 0.f);

#define LOAD_STAGE(s, kk)                                                          \
    do {                                                                           \
        _Pragma("unroll")                                                          \
        for (int i = 0; i < 6; i++) {                                              \
            int id = tid + i * 256; int r = id >> 3, c4 = id & 7;                  \
            uint32_t dst = smem_u32 + ((((s) ? OFF_A1 : OFF_A0) + r * AP + c4 * 4) << 2); \
            cpasync16(dst, Qb + r * Dd + (kk) * BK + c4 * 4);                      \
        }                                                                          \
        _Pragma("unroll")                                                          \
        for (int i = 0; i < 4; i++) {                                              \
            int id = tid + i * 256; int r = id >> 3, c4 = id & 7;                  \
            uint32_t dst = smem_u32 + ((((s) ? OFF_B1 : OFF_B0) + r * AP + c4 * 4) << 2); \
            cpasync16(dst, Kb + r * Dd + (kk) * BK + c4 * 4);                      \
        }                                                                          \
    } while (0)

    LOAD_STAGE(0, 0);
    asm volatile("cp.async.commit_group;\n");
    LOAD_STAGE(1, 1);
    asm volatile("cp.async.commit_group;\n");

    for (int kk = 0; kk < 8; kk++) {
        asm volatile("cp.async.wait_group 1;\n");
        __syncthreads();
        const float* As = smem + ((kk & 1) ? OFF_A1 : OFF_A0);
        const float* Bs = smem + ((kk & 1) ? OFF_B1 : OFF_B0);

#pragma unroll
        for (int ks = 0; ks < 4; ks++) {
            const int k0 = ks * 8;
            uint32_t a[3][4];
#pragma unroll
            for (int mi = 0; mi < 3; mi++) {
                const int r0 = (wm * 48 + mi * 16 + g8) * AP;
                a[mi][0] = __float_as_uint(As[r0 + k0 + tg]);
                a[mi][1] = __float_as_uint(As[r0 + 8 * AP + k0 + tg]);
                a[mi][2] = __float_as_uint(As[r0 + k0 + tg + 4]);
                a[mi][3] = __float_as_uint(As[r0 + 8 * AP + k0 + tg + 4]);
            }
            uint32_t b[8][2];
#pragma unroll
            for (int ni = 0; ni < 8; ni++) {
                const int c = (wn * 64 + ni * 8 + g8) * AP;
                b[ni][0] = __float_as_uint(Bs[c + k0 + tg]);
                b[ni][1] = __float_as_uint(Bs[c + k0 + tg + 4]);
            }
#pragma unroll
            for (int mi = 0; mi < 3; mi++)
#pragma unroll
                for (int ni = 0; ni < 8; ni++) mma8(acc[mi][ni], a[mi], b[ni]);
        }
        __syncthreads();
        if (kk + 2 < 8) LOAD_STAGE(kk & 1, kk + 2);
        asm volatile("cp.async.commit_group;\n");
    }
#undef LOAD_STAGE

    if (!is_z) {
        // ---- per-row lse over this 128-col tile ----
        float* red_m = smem + OFF_RM;
        float* red_s = smem + OFF_RS;
#pragma unroll
        for (int mi = 0; mi < 3; mi++) {
#pragma unroll
            for (int half = 0; half < 2; half++) {
                float v[16];
#pragma unroll
                for (int ni = 0; ni < 8; ni++) {
                    v[2 * ni]     = half ? acc[mi][ni].z : acc[mi][ni].x;
                    v[2 * ni + 1] = half ? acc[mi][ni].w : acc[mi][ni].y;
                }
                float m = v[0];
#pragma unroll
                for (int i = 1; i < 16; i++) m = fmaxf(m, v[i]);
                float s = 0.f;
#pragma unroll
                for (int i = 0; i < 16; i++) s += __expf(v[i] - m);
#pragma unroll
                for (int o = 1; o < 4; o <<= 1) {
                    float om = __shfl_xor_sync(0xffffffffu, m, o);
                    float os = __shfl_xor_sync(0xffffffffu, s, o);
                    float nm = fmaxf(m, om);
                    s = s * __expf(m - nm) + os * __expf(om - nm);
                    m = nm;
                }
                if (tg == 0) {
                    int rl = wm * 48 + mi * 16 + half * 8 + g8;
                    red_m[rl * 2 + wn] = m;
                    red_s[rl * 2 + wn] = s;
                }
            }
        }
        __syncthreads();
        if (tid < BM) {
            float m = red_m[tid * 2], s = red_s[tid * 2];
            float om = red_m[tid * 2 + 1], os = red_s[tid * 2 + 1];
            float nm = fmaxf(m, om);
            s = s * __expf(m - nm) + os * __expf(om - nm);
            int grow = mtile * BM + tid;
            if (grow < NQ) d_part[grow * NT_Q + ntile] = nm + __logf(s);
        }
    } else {
        // ---- write raw sims for the z-key tiles ----
        const int col0 = (ntile - NT_Q) * BN + wn * 64;
#pragma unroll
        for (int mi = 0; mi < 3; mi++) {
            const int row0 = mtile * BM + wm * 48 + mi * 16 + g8;
#pragma unroll
            for (int ni = 0; ni < 8; ni++) {
                const int c = col0 + ni * 8 + 2 * tg;
                *(float2*)&d_Sim[row0 * Nn + c]       = make_float2(acc[mi][ni].x, acc[mi][ni].y);
                *(float2*)&d_Sim[(row0 + 8) * Nn + c] = make_float2(acc[mi][ni].z, acc[mi][ni].w);
            }
        }
    }
}

// ---------------- kernel 3: reduce 1024 partial lse -> lse_q per row ----------------
__global__ void k_reduce() {
    const int row = blockIdx.x, tid = threadIdx.x;
    const float* p = d_part + row * NT_Q;
    float vals[4];
    float m = -INFINITY;
#pragma unroll
    for (int i = 0; i < 4; i++) {
        vals[i] = p[tid + i * 256];
        m = fmaxf(m, vals[i]);
    }
    __shared__ float sm[256];
    sm[tid] = m;
    __syncthreads();
    for (int st = 128; st; st >>= 1) {
        if (tid < st) sm[tid] = fmaxf(sm[tid], sm[tid + st]);
        __syncthreads();
    }
    const float M = sm[0];
    __syncthreads();
    float s = 0.f;
#pragma unroll
    for (int i = 0; i < 4; i++) s += __expf(vals[i] - M);
    sm[tid] = s;
    __syncthreads();
    for (int st = 128; st; st >>= 1) {
        if (tid < st) sm[tid] += sm[tid + st];
        __syncthreads();
    }
    if (tid == 0) d_lseq[row] = M + __logf(sm[0]);
}

// ---------------- kernel 4: masked lse over precomputed sims + combine ----------------
__global__ void k_masked() {
    __shared__ float rm[256], rs[256];
    __shared__ float posbuf[Ll];
    __shared__ float s_pos;
    __shared__ float s_lse;

    const int bid = blockIdx.x, tid = threadIdx.x;
    const bool is_g = (bid >= Nn);
    const int a = bid;
    const int gb = bid - Nn;

    float m = -INFINITY, sacc = 0.f;
#pragma unroll
    for (int rep = 0; rep < 2; rep++) {
        const int j = tid + rep * 256;
        const float v = d_Sim[bid * Nn + j];
        bool masked = false;
        if (is_g) {
            if ((j >> 5) == gb) { posbuf[j & 31] = v; masked = true; }
        } else {
            if (j == a) masked = true;
            else if (j == a + 1) { s_pos = v; masked = true; }
        }
        if (!masked) {
            if (v > m) { sacc = sacc * expf(m - v) + 1.f; m = v; }
            else       { sacc += expf(v - m); }
        }
    }

    rm[tid] = m; rs[tid] = sacc;
    __syncthreads();
    for (int st = 128; st; st >>= 1) {
        if (tid < st) {
            float m1 = rm[tid], s1 = rs[tid];
            float m2 = rm[tid + st], s2 = rs[tid + st];
            float nm = fmaxf(m1, m2);
            float ns;
            if (nm == -INFINITY) ns = 0.f;
            else ns = s1 * expf(m1 - nm) + s2 * expf(m2 - nm);
            rm[tid] = nm; rs[tid] = ns;
        }
        __syncthreads();
    }
    if (tid == 0) {
        const float lneg = rm[0] + logf(rs[0]);
        const float lq = d_lseq[bid];
        const float hi = fmaxf(lneg, lq), lo = fminf(lneg, lq);
        s_lse = hi + log1pf(expf(lo - hi));
    }
    __syncthreads();

    if (!is_g) {
        const int t = a & (Ll - 1);
        if (t < Ll - 1 && tid == 0) {
            d_llterms[(a >> 5) * (Ll - 1) + t] = softplusf(s_lse - s_pos);
        }
    } else {
        if (tid < Ll) {
            d_glterms[gb * Ll + tid] = softplusf(s_lse - posbuf[tid]);
        }
    }
}

// ---------------- kernel 5: deterministic final reduction ----------------
__global__ void k_final(const float* __restrict__ z, float* __restrict__ out) {
    __shared__ float sm[256];
    const int tid = threadIdx.x;

    float sll = 0.f;
    for (int i = tid; i < MLL; i += 256) sll += d_llterms[i];
    float sgl = 0.f;
    for (int i = tid; i < Nn; i += 256) sgl += d_glterms[i];
    float ssm = 0.f;
    const int total = Bb * (Ll - 1) * Dd;
    for (int i = tid; i < total; i += 256) {
        int b = i / ((Ll - 1) * Dd);
        int r = i % ((Ll - 1) * Dd);
        int t = r >> 8, d = r & 255;
        float df = z[(b * Ll + t + 1) * Dd + d] - z[(b * Ll + t) * Dd + d];
        ssm += df * df;
    }

    float Sll, Sgl, Ssm;
    sm[tid] = sll; __syncthreads();
    for (int st = 128; st; st >>= 1) { if (tid < st) sm[tid] += sm[tid + st]; __syncthreads(); }
    Sll = sm[0]; __syncthreads();
    sm[tid] = sgl; __syncthreads();
    for (int st = 128; st; st >>= 1) { if (tid < st) sm[tid] += sm[tid + st]; __syncthreads(); }
    Sgl = sm[0]; __syncthreads();
    sm[tid] = ssm; __syncthreads();
    for (int st = 128; st; st >>= 1) { if (tid < st) sm[tid] += sm[tid + st]; __syncthreads(); }
    Ssm = sm[0];

    if (tid == 0) {
        out[0] = Sll / (float)MLL + 0.5f * (Sgl / (float)Nn) + 0.1f * (Ssm / (float)MLL);
    }
}

// ---------------- launch ----------------
extern "C" void kernel_launch(void* const* d_in, const int* in_sizes, int n_in,
                              void* d_out, int out_size) {
    const float* z  = (const float*)d_in[0];   // z_t  [16,32,256]
    const float* g  = (const float*)d_in[1];   // g    [16,256]
    const float* mq = (const float*)d_in[3];   // memory_queue [131072,256]
    float* out = (float*)d_out;

    cudaFuncSetAttribute(k_gemm, cudaFuncAttributeMaxDynamicSharedMemorySize, SMEM_BYTES);

    k_prep<<<NQP, 256>>>(z, g);
    dim3 grid(MT, NT);     // mtile fastest -> the 3 blocks sharing a key tile run together
    k_gemm<<<grid, 256, SMEM_BYTES>>>(mq, z);
    k_reduce<<<NQ, 256>>>();
    k_masked<<<NQ, 256>>>();
    k_final<<<1, 256>>>(z, out);
}

// round 7
// speedup vs baseline: 1.5561x; 1.1498x over previous
#include <cuda_runtime.h>
#include <cuda_bf16.h>
#include <cstdint>
#include <math.h>

// ---------------- problem constants ----------------
#define INV_TAU (1.0f / 0.07f)
constexpr int Bb = 16, Ll = 32, Dd = 256, Kk = 131072;
constexpr int Nn = 512;          // B*L frames
constexpr int NQ = 528;          // 512 z rows + 16 g rows
constexpr int NQP = 576;         // padded to 3*192
constexpr int BM = 192, BN = 128, BK = 32;
constexpr int NT_Q = Kk / BN;    // 1024 queue tiles
constexpr int NT_Z = Nn / BN;    // 4 z-key tiles
constexpr int NT = NT_Q + NT_Z;  // 1028
constexpr int MT = NQP / BM;     // 3
constexpr int MLL = Bb * (Ll - 1);

// smem byte layout: bf16 tiles, pitch 40 bf16 (80B) -> conflict-free frag reads
constexpr int APB = 40;                       // bf16 elements per row slot
constexpr int A_BYTES = BM * APB * 2;         // 15360
constexpr int B_BYTES = BN * APB * 2;         // 10240
constexpr int OFF_A0 = 0;
constexpr int OFF_A1 = A_BYTES;               // 15360
constexpr int OFF_B0 = 2 * A_BYTES;           // 30720
constexpr int OFF_B1 = 2 * A_BYTES + B_BYTES; // 40960
constexpr int OFF_RED = 2 * A_BYTES + 2 * B_BYTES;  // 51200
constexpr int SMEM_BYTES = OFF_RED + BM * 2 * 4 * 2; // + red_m/red_s = 54272

// ---------------- device scratch ----------------
__device__ __nv_bfloat16 d_mqbf[Kk * Dd];     // 64 MB bf16 queue
__device__ __nv_bfloat16 d_Qbuf[NQP * Dd];    // scaled bf16 queries
__device__ __nv_bfloat16 d_zbf[Nn * Dd];      // unscaled bf16 z keys
__device__ float d_part[NQP * NT_Q];
__device__ float d_lseq[NQ];
__device__ float d_Sim[NQP * Nn];
__device__ float d_llterms[MLL];
__device__ float d_glterms[Nn];

// ---------------- helpers ----------------
__device__ __forceinline__ void mma16(float4& d, const uint32_t* a, const uint32_t* b) {
    asm volatile(
        "mma.sync.aligned.m16n8k16.row.col.f32.bf16.bf16.f32 "
        "{%0,%1,%2,%3}, {%4,%5,%6,%7}, {%8,%9}, {%0,%1,%2,%3};\n"
        : "+f"(d.x), "+f"(d.y), "+f"(d.z), "+f"(d.w)
        : "r"(a[0]), "r"(a[1]), "r"(a[2]), "r"(a[3]), "r"(b[0]), "r"(b[1]));
}
__device__ __forceinline__ void cpasync16(uint32_t dst, const void* src) {
    asm volatile("cp.async.cg.shared.global [%0], [%1], 16;\n" :: "r"(dst), "l"(src));
}
__device__ __forceinline__ float softplusf(float x) {
    return (x > 0.f) ? x + log1pf(expf(-x)) : log1pf(expf(x));
}
__device__ __forceinline__ uint32_t bf2_bits(float lo, float hi) {
    __nv_bfloat162 p = __float22bfloat162_rn(make_float2(lo, hi));
    return *reinterpret_cast<uint32_t*>(&p);
}

// ---------------- kernel 0: queue fp32 -> bf16 (rn) ----------------
__global__ void k_conv(const float* __restrict__ mq) {
    const int i = blockIdx.x * blockDim.x + threadIdx.x;   // 8 elems / thread
    const float4 v0 = *(const float4*)(mq + i * 8);
    const float4 v1 = *(const float4*)(mq + i * 8 + 4);
    uint4 o;
    o.x = bf2_bits(v0.x, v0.y);
    o.y = bf2_bits(v0.z, v0.w);
    o.z = bf2_bits(v1.x, v1.y);
    o.w = bf2_bits(v1.z, v1.w);
    *(uint4*)(d_mqbf + i * 8) = o;
}

// ---------------- kernel 1: queries (scaled) + z keys (unscaled) -> bf16 ----------------
__global__ void k_prep(const float* __restrict__ z, const float* __restrict__ g) {
    const int i = blockIdx.x * blockDim.x + threadIdx.x;   // 0 .. NQP*Dd-1
    const int row = i >> 8, d = i & 255;
    float v = 0.f;
    if (row < Nn)       v = z[i] * INV_TAU;
    else if (row < NQ)  v = g[(row - Nn) * Dd + d] * INV_TAU;
    d_Qbuf[i] = __float2bfloat16_rn(v);
    if (i < Nn * Dd) d_zbf[i] = __float2bfloat16_rn(z[i]);
}

// ---------------- kernel 2: pipelined bf16 GEMM (queries x [queue; z]) ----------------
__global__ __launch_bounds__(256, 1) void k_gemm() {
    extern __shared__ char smc[];
    const uint32_t smem_u32 = (uint32_t)__cvta_generic_to_shared(smc);

    const int tid  = threadIdx.x;
    const int warp = tid >> 5, lane = tid & 31;
    const int wm = warp >> 1, wn = warp & 1;   // 4 x 2 warp grid
    const int g8 = lane >> 2, tg = lane & 3;
    const int mtile = blockIdx.x;
    const int ntile = blockIdx.y;
    const bool is_z = (ntile >= NT_Q);

    const __nv_bfloat16* Qb = d_Qbuf + mtile * BM * Dd;
    const __nv_bfloat16* Kb = is_z ? (d_zbf + (size_t)(ntile - NT_Q) * BN * Dd)
                                   : (d_mqbf + (size_t)ntile * BN * Dd);

    float4 acc[3][8];
#pragma unroll
    for (int mi = 0; mi < 3; mi++)
#pragma unroll
        for (int ni = 0; ni < 8; ni++) acc[mi][ni] = make_float4(0.f, 0.f, 0.f, 0.f);

    // 16B = 8 bf16. A: 192*32 -> 768 xfers (3/thread). B: 128*32 -> 512 (2/thread).
#define LOAD_STAGE(s, kk)                                                            \
    do {                                                                             \
        _Pragma("unroll")                                                            \
        for (int i = 0; i < 3; i++) {                                                \
            int id = tid + i * 256; int r = id >> 2, c8 = id & 3;                    \
            uint32_t dst = smem_u32 + ((s) ? OFF_A1 : OFF_A0) + (r * APB + c8 * 8) * 2; \
            cpasync16(dst, Qb + r * Dd + (kk) * BK + c8 * 8);                        \
        }                                                                            \
        _Pragma("unroll")                                                            \
        for (int i = 0; i < 2; i++) {                                                \
            int id = tid + i * 256; int r = id >> 2, c8 = id & 3;                    \
            uint32_t dst = smem_u32 + ((s) ? OFF_B1 : OFF_B0) + (r * APB + c8 * 8) * 2; \
            cpasync16(dst, Kb + r * Dd + (kk) * BK + c8 * 8);                        \
        }                                                                            \
    } while (0)

    LOAD_STAGE(0, 0);
    asm volatile("cp.async.commit_group;\n");
    LOAD_STAGE(1, 1);
    asm volatile("cp.async.commit_group;\n");

    for (int kk = 0; kk < 8; kk++) {
        asm volatile("cp.async.wait_group 1;\n");
        __syncthreads();
        const __nv_bfloat16* As =
            (const __nv_bfloat16*)(smc + ((kk & 1) ? OFF_A1 : OFF_A0));
        const __nv_bfloat16* Bs =
            (const __nv_bfloat16*)(smc + ((kk & 1) ? OFF_B1 : OFF_B0));

#pragma unroll
        for (int ks = 0; ks < 2; ks++) {
            const int k0 = ks * 16;
            uint32_t a[3][4];
#pragma unroll
            for (int mi = 0; mi < 3; mi++) {
                const int r0 = (wm * 48 + mi * 16 + g8) * APB;
                a[mi][0] = *(const uint32_t*)&As[r0 + k0 + tg * 2];
                a[mi][1] = *(const uint32_t*)&As[r0 + 8 * APB + k0 + tg * 2];
                a[mi][2] = *(const uint32_t*)&As[r0 + k0 + tg * 2 + 8];
                a[mi][3] = *(const uint32_t*)&As[r0 + 8 * APB + k0 + tg * 2 + 8];
            }
            uint32_t b[8][2];
#pragma unroll
            for (int ni = 0; ni < 8; ni++) {
                const int c = (wn * 64 + ni * 8 + g8) * APB;
                b[ni][0] = *(const uint32_t*)&Bs[c + k0 + tg * 2];
                b[ni][1] = *(const uint32_t*)&Bs[c + k0 + tg * 2 + 8];
            }
#pragma unroll
            for (int mi = 0; mi < 3; mi++)
#pragma unroll
                for (int ni = 0; ni < 8; ni++) mma16(acc[mi][ni], a[mi], b[ni]);
        }
        __syncthreads();
        if (kk + 2 < 8) LOAD_STAGE(kk & 1, kk + 2);
        asm volatile("cp.async.commit_group;\n");
    }
#undef LOAD_STAGE

    if (!is_z) {
        // ---- per-row lse over this 128-col tile ----
        float* red_m = (float*)(smc + OFF_RED);
        float* red_s = red_m + BM * 2;
#pragma unroll
        for (int mi = 0; mi < 3; mi++) {
#pragma unroll
            for (int half = 0; half < 2; half++) {
                float v[16];
#pragma unroll
                for (int ni = 0; ni < 8; ni++) {
                    v[2 * ni]     = half ? acc[mi][ni].z : acc[mi][ni].x;
                    v[2 * ni + 1] = half ? acc[mi][ni].w : acc[mi][ni].y;
                }
                float m = v[0];
#pragma unroll
                for (int i = 1; i < 16; i++) m = fmaxf(m, v[i]);
                float s = 0.f;
#pragma unroll
                for (int i = 0; i < 16; i++) s += __expf(v[i] - m);
#pragma unroll
                for (int o = 1; o < 4; o <<= 1) {
                    float om = __shfl_xor_sync(0xffffffffu, m, o);
                    float os = __shfl_xor_sync(0xffffffffu, s, o);
                    float nm = fmaxf(m, om);
                    s = s * __expf(m - nm) + os * __expf(om - nm);
                    m = nm;
                }
                if (tg == 0) {
                    int rl = wm * 48 + mi * 16 + half * 8 + g8;
                    red_m[rl * 2 + wn] = m;
                    red_s[rl * 2 + wn] = s;
                }
            }
        }
        __syncthreads();
        if (tid < BM) {
            float m = red_m[tid * 2], s = red_s[tid * 2];
            float om = red_m[tid * 2 + 1], os = red_s[tid * 2 + 1];
            float nm = fmaxf(m, om);
            s = s * __expf(m - nm) + os * __expf(om - nm);
            int grow = mtile * BM + tid;
            if (grow < NQ) d_part[grow * NT_Q + ntile] = nm + __logf(s);
        }
    } else {
        // ---- write raw sims for the z-key tiles ----
        const int col0 = (ntile - NT_Q) * BN + wn * 64;
#pragma unroll
        for (int mi = 0; mi < 3; mi++) {
            const int row0 = mtile * BM + wm * 48 + mi * 16 + g8;
#pragma unroll
            for (int ni = 0; ni < 8; ni++) {
                const int c = col0 + ni * 8 + 2 * tg;
                *(float2*)&d_Sim[row0 * Nn + c]       = make_float2(acc[mi][ni].x, acc[mi][ni].y);
                *(float2*)&d_Sim[(row0 + 8) * Nn + c] = make_float2(acc[mi][ni].z, acc[mi][ni].w);
            }
        }
    }
}

// ---------------- kernel 3: reduce 1024 partial lse -> lse_q per row ----------------
__global__ void k_reduce() {
    const int row = blockIdx.x, tid = threadIdx.x;
    const float* p = d_part + row * NT_Q;
    float vals[4];
    float m = -INFINITY;
#pragma unroll
    for (int i = 0; i < 4; i++) { vals[i] = p[tid + i * 256]; m = fmaxf(m, vals[i]); }
    __shared__ float sm[256];
    sm[tid] = m; __syncthreads();
    for (int st = 128; st; st >>= 1) {
        if (tid < st) sm[tid] = fmaxf(sm[tid], sm[tid + st]);
        __syncthreads();
    }
    const float M = sm[0]; __syncthreads();
    float s = 0.f;
#pragma unroll
    for (int i = 0; i < 4; i++) s += __expf(vals[i] - M);
    sm[tid] = s; __syncthreads();
    for (int st = 128; st; st >>= 1) {
        if (tid < st) sm[tid] += sm[tid + st];
        __syncthreads();
    }
    if (tid == 0) d_lseq[row] = M + __logf(sm[0]);
}

// ---------------- kernel 4: masked lse over precomputed sims + combine ----------------
__global__ void k_masked() {
    __shared__ float rm[256], rs[256];
    __shared__ float posbuf[Ll];
    __shared__ float s_pos, s_lse;
    const int bid = blockIdx.x, tid = threadIdx.x;
    const bool is_g = (bid >= Nn);
    const int a = bid, gb = bid - Nn;

    float m = -INFINITY, sacc = 0.f;
#pragma unroll
    for (int rep = 0; rep < 2; rep++) {
        const int j = tid + rep * 256;
        const float v = d_Sim[bid * Nn + j];
        bool masked = false;
        if (is_g) { if ((j >> 5) == gb) { posbuf[j & 31] = v; masked = true; } }
        else {
            if (j == a) masked = true;
            else if (j == a + 1) { s_pos = v; masked = true; }
        }
        if (!masked) {
            if (v > m) { sacc = sacc * expf(m - v) + 1.f; m = v; }
            else       { sacc += expf(v - m); }
        }
    }
    rm[tid] = m; rs[tid] = sacc;
    __syncthreads();
    for (int st = 128; st; st >>= 1) {
        if (tid < st) {
            float m1 = rm[tid], s1 = rs[tid];
            float m2 = rm[tid + st], s2 = rs[tid + st];
            float nm = fmaxf(m1, m2);
            float ns = (nm == -INFINITY) ? 0.f : s1 * expf(m1 - nm) + s2 * expf(m2 - nm);
            rm[tid] = nm; rs[tid] = ns;
        }
        __syncthreads();
    }
    if (tid == 0) {
        const float lneg = rm[0] + logf(rs[0]);
        const float lq = d_lseq[bid];
        const float hi = fmaxf(lneg, lq), lo = fminf(lneg, lq);
        s_lse = hi + log1pf(expf(lo - hi));
    }
    __syncthreads();
    if (!is_g) {
        const int t = a & (Ll - 1);
        if (t < Ll - 1 && tid == 0)
            d_llterms[(a >> 5) * (Ll - 1) + t] = softplusf(s_lse - s_pos);
    } else {
        if (tid < Ll) d_glterms[gb * Ll + tid] = softplusf(s_lse - posbuf[tid]);
    }
}

// ---------------- kernel 5: deterministic final reduction ----------------
__global__ void k_final(const float* __restrict__ z, float* __restrict__ out) {
    __shared__ float sm[256];
    const int tid = threadIdx.x;
    float sll = 0.f;
    for (int i = tid; i < MLL; i += 256) sll += d_llterms[i];
    float sgl = 0.f;
    for (int i = tid; i < Nn; i += 256) sgl += d_glterms[i];
    float ssm = 0.f;
    const int total = Bb * (Ll - 1) * Dd;
    for (int i = tid; i < total; i += 256) {
        int b = i / ((Ll - 1) * Dd);
        int r = i % ((Ll - 1) * Dd);
        int t = r >> 8, d = r & 255;
        float df = z[(b * Ll + t + 1) * Dd + d] - z[(b * Ll + t) * Dd + d];
        ssm += df * df;
    }
    float Sll, Sgl, Ssm;
    sm[tid] = sll; __syncthreads();
    for (int st = 128; st; st >>= 1) { if (tid < st) sm[tid] += sm[tid + st]; __syncthreads(); }
    Sll = sm[0]; __syncthreads();
    sm[tid] = sgl; __syncthreads();
    for (int st = 128; st; st >>= 1) { if (tid < st) sm[tid] += sm[tid + st]; __syncthreads(); }
    Sgl = sm[0]; __syncthreads();
    sm[tid] = ssm; __syncthreads();
    for (int st = 128; st; st >>= 1) { if (tid < st) sm[tid] += sm[tid + st]; __syncthreads(); }
    Ssm = sm[0];
    if (tid == 0)
        out[0] = Sll / (float)MLL + 0.5f * (Sgl / (float)Nn) + 0.1f * (Ssm / (float)MLL);
}

// ---------------- launch ----------------
extern "C" void kernel_launch(void* const* d_in, const int* in_sizes, int n_in,
                              void* d_out, int out_size) {
    const float* z  = (const float*)d_in[0];
    const float* g  = (const float*)d_in[1];
    const float* mq = (const float*)d_in[3];
    float* out = (float*)d_out;

    cudaFuncSetAttribute(k_gemm, cudaFuncAttributeMaxDynamicSharedMemorySize, SMEM_BYTES);

    k_conv<<<Kk * Dd / 8 / 256, 256>>>(mq);
    k_prep<<<NQP, 256>>>(z, g);
    dim3 grid(MT, NT);     // mtile fastest -> 3 blocks sharing a key tile run together
    k_gemm<<<grid, 256, SMEM_BYTES>>>();
    k_reduce<<<NQ, 256>>>();
    k_masked<<<NQ, 256>>>();
    k_final<<<1, 256>>>(z, out);
}

// round 8
// speedup vs baseline: 1.8241x; 1.1723x over previous
#include <cuda_runtime.h>
#include <cuda_bf16.h>
#include <cstdint>
#include <math.h>

// ---------------- problem constants ----------------
#define INV_TAU (1.0f / 0.07f)
constexpr int Bb = 16, Ll = 32, Dd = 256, Kk = 131072;
constexpr int Nn = 512;          // B*L frames
constexpr int NQ = 528;          // 512 z rows + 16 g rows
constexpr int NQP = 576;         // padded to 3*192
constexpr int BM = 192, BN = 128, BK = 32;
constexpr int NT_Q = Kk / BN;    // 1024 queue tiles
constexpr int NT_Z = Nn / BN;    // 4 z-key tiles
constexpr int NT = NT_Q + NT_Z;  // 1028
constexpr int MT = NQP / BM;     // 3
constexpr int MLL = Bb * (Ll - 1);

// smem layout: A bf16 pitch 40 (80B rows), B fp32 pitch 40 (160B rows); 3 stages
constexpr int APB = 40;                       // A: bf16 elems per row slot
constexpr int A_BYTES = BM * APB * 2;         // 15360 per stage
constexpr int B_BYTES = BN * APB * 4;         // 20480 per stage (fp32)
constexpr int OFF_B = 3 * A_BYTES;            // 46080
constexpr int OFF_RED = OFF_B + 3 * B_BYTES;  // 107520
constexpr int SMEM_BYTES = OFF_RED + BM * 2 * 4 * 2;  // 110592

// ---------------- device scratch ----------------
__device__ __nv_bfloat16 d_Qbuf[NQP * Dd];    // scaled bf16 queries
__device__ float d_part[NQP * NT_Q];
__device__ float d_Sim[NQP * Nn];
__device__ float d_llterms[MLL];
__device__ float d_glterms[Nn];

// ---------------- helpers ----------------
__device__ __forceinline__ void mma16(float4& d, const uint32_t* a, const uint32_t* b) {
    asm volatile(
        "mma.sync.aligned.m16n8k16.row.col.f32.bf16.bf16.f32 "
        "{%0,%1,%2,%3}, {%4,%5,%6,%7}, {%8,%9}, {%0,%1,%2,%3};\n"
        : "+f"(d.x), "+f"(d.y), "+f"(d.z), "+f"(d.w)
        : "r"(a[0]), "r"(a[1]), "r"(a[2]), "r"(a[3]), "r"(b[0]), "r"(b[1]));
}
__device__ __forceinline__ void cpasync16(uint32_t dst, const void* src) {
    asm volatile("cp.async.cg.shared.global [%0], [%1], 16;\n" :: "r"(dst), "l"(src));
}
__device__ __forceinline__ float softplusf(float x) {
    return (x > 0.f) ? x + log1pf(expf(-x)) : log1pf(expf(x));
}
__device__ __forceinline__ uint32_t bf2_bits(float lo, float hi) {
    __nv_bfloat162 p = __float22bfloat162_rn(make_float2(lo, hi));
    return *reinterpret_cast<uint32_t*>(&p);
}

// ---------------- kernel 1: queries (scaled) -> bf16 ----------------
__global__ void k_prep(const float* __restrict__ z, const float* __restrict__ g) {
    const int i = blockIdx.x * blockDim.x + threadIdx.x;   // 0 .. NQP*Dd-1
    const int row = i >> 8, d = i & 255;
    float v = 0.f;
    if (row < Nn)       v = z[i] * INV_TAU;
    else if (row < NQ)  v = g[(row - Nn) * Dd + d] * INV_TAU;
    d_Qbuf[i] = __float2bfloat16_rn(v);
}

// ---------------- kernel 2: 3-stage pipelined bf16 GEMM, fp32 keys in smem ----------------
__global__ __launch_bounds__(256, 1) void k_gemm(const float* __restrict__ mq,
                                                 const float* __restrict__ zk) {
    extern __shared__ char smc[];
    const uint32_t smem_u32 = (uint32_t)__cvta_generic_to_shared(smc);

    const int tid  = threadIdx.x;
    const int warp = tid >> 5, lane = tid & 31;
    const int wm = warp >> 1, wn = warp & 1;   // 4 x 2 warp grid
    const int g8 = lane >> 2, tg = lane & 3;
    const int mtile = blockIdx.x;
    const int ntile = blockIdx.y;
    const bool is_z = (ntile >= NT_Q);

    const __nv_bfloat16* Qb = d_Qbuf + mtile * BM * Dd;
    const float* Kb = is_z ? (zk + (size_t)(ntile - NT_Q) * BN * Dd)
                           : (mq + (size_t)ntile * BN * Dd);

    float4 acc[3][8];
#pragma unroll
    for (int mi = 0; mi < 3; mi++)
#pragma unroll
        for (int ni = 0; ni < 8; ni++) acc[mi][ni] = make_float4(0.f, 0.f, 0.f, 0.f);

    // A: 192x32 bf16 = 768 x16B (3/thread). B: 128x32 fp32 = 1024 x16B (4/thread).
#define LOAD_STAGE(s, kk)                                                            \
    do {                                                                             \
        _Pragma("unroll")                                                            \
        for (int i = 0; i < 3; i++) {                                                \
            int id = tid + i * 256; int r = id >> 2, c8 = id & 3;                    \
            uint32_t dst = smem_u32 + (s) * A_BYTES + (r * APB + c8 * 8) * 2;        \
            cpasync16(dst, Qb + r * Dd + (kk) * BK + c8 * 8);                        \
        }                                                                            \
        _Pragma("unroll")                                                            \
        for (int i = 0; i < 4; i++) {                                                \
            int id = tid + i * 256; int r = id >> 3, c4 = id & 7;                    \
            uint32_t dst = smem_u32 + OFF_B + (s) * B_BYTES + (r * APB + c4 * 4) * 4; \
            cpasync16(dst, Kb + r * Dd + (kk) * BK + c4 * 4);                        \
        }                                                                            \
    } while (0)

    LOAD_STAGE(0, 0);
    asm volatile("cp.async.commit_group;\n");
    LOAD_STAGE(1, 1);
    asm volatile("cp.async.commit_group;\n");

#pragma unroll 1
    for (int kk = 0; kk < 8; kk++) {
        asm volatile("cp.async.wait_group 1;\n");
        __syncthreads();
        const int s = kk - (kk >= 3 ? 3 : 0) - (kk >= 6 ? 3 : 0);   // kk % 3
        if (kk + 2 < 8) {
            const int s2 = (kk + 2) - ((kk + 2) >= 3 ? 3 : 0) - ((kk + 2) >= 6 ? 3 : 0);
            LOAD_STAGE(s2, kk + 2);
        }
        asm volatile("cp.async.commit_group;\n");

        const __nv_bfloat16* As = (const __nv_bfloat16*)(smc + s * A_BYTES);
        const float* Bs = (const float*)(smc + OFF_B + s * B_BYTES);

#pragma unroll
        for (int ks = 0; ks < 2; ks++) {
            const int k0 = ks * 16;
            uint32_t a[3][4];
#pragma unroll
            for (int mi = 0; mi < 3; mi++) {
                const int r0 = (wm * 48 + mi * 16 + g8) * APB;
                a[mi][0] = *(const uint32_t*)&As[r0 + k0 + tg * 2];
                a[mi][1] = *(const uint32_t*)&As[r0 + 8 * APB + k0 + tg * 2];
                a[mi][2] = *(const uint32_t*)&As[r0 + k0 + tg * 2 + 8];
                a[mi][3] = *(const uint32_t*)&As[r0 + 8 * APB + k0 + tg * 2 + 8];
            }
            uint32_t b[8][2];
#pragma unroll
            for (int ni = 0; ni < 8; ni++) {
                const float* bp = &Bs[(wn * 64 + ni * 8 + g8) * APB + k0 + tg * 2];
                float2 v0 = *(const float2*)bp;
                float2 v1 = *(const float2*)(bp + 8);
                b[ni][0] = bf2_bits(v0.x, v0.y);
                b[ni][1] = bf2_bits(v1.x, v1.y);
            }
#pragma unroll
            for (int mi = 0; mi < 3; mi++)
#pragma unroll
                for (int ni = 0; ni < 8; ni++) mma16(acc[mi][ni], a[mi], b[ni]);
        }
    }
#undef LOAD_STAGE

    if (!is_z) {
        // ---- per-row lse over this 128-col tile ----
        float* red_m = (float*)(smc + OFF_RED);
        float* red_s = red_m + BM * 2;
#pragma unroll
        for (int mi = 0; mi < 3; mi++) {
#pragma unroll
            for (int half = 0; half < 2; half++) {
                float v[16];
#pragma unroll
                for (int ni = 0; ni < 8; ni++) {
                    v[2 * ni]     = half ? acc[mi][ni].z : acc[mi][ni].x;
                    v[2 * ni + 1] = half ? acc[mi][ni].w : acc[mi][ni].y;
                }
                float m = v[0];
#pragma unroll
                for (int i = 1; i < 16; i++) m = fmaxf(m, v[i]);
                float s = 0.f;
#pragma unroll
                for (int i = 0; i < 16; i++) s += __expf(v[i] - m);
#pragma unroll
                for (int o = 1; o < 4; o <<= 1) {
                    float om = __shfl_xor_sync(0xffffffffu, m, o);
                    float os = __shfl_xor_sync(0xffffffffu, s, o);
                    float nm = fmaxf(m, om);
                    s = s * __expf(m - nm) + os * __expf(om - nm);
                    m = nm;
                }
                if (tg == 0) {
                    int rl = wm * 48 + mi * 16 + half * 8 + g8;
                    red_m[rl * 2 + wn] = m;
                    red_s[rl * 2 + wn] = s;
                }
            }
        }
        __syncthreads();
        if (tid < BM) {
            float m = red_m[tid * 2], s = red_s[tid * 2];
            float om = red_m[tid * 2 + 1], os = red_s[tid * 2 + 1];
            float nm = fmaxf(m, om);
            s = s * __expf(m - nm) + os * __expf(om - nm);
            int grow = mtile * BM + tid;
            if (grow < NQ) d_part[grow * NT_Q + ntile] = nm + __logf(s);
        }
    } else {
        // ---- write raw sims for the z-key tiles ----
        const int col0 = (ntile - NT_Q) * BN + wn * 64;
#pragma unroll
        for (int mi = 0; mi < 3; mi++) {
            const int row0 = mtile * BM + wm * 48 + mi * 16 + g8;
#pragma unroll
            for (int ni = 0; ni < 8; ni++) {
                const int c = col0 + ni * 8 + 2 * tg;
                *(float2*)&d_Sim[row0 * Nn + c]       = make_float2(acc[mi][ni].x, acc[mi][ni].y);
                *(float2*)&d_Sim[(row0 + 8) * Nn + c] = make_float2(acc[mi][ni].z, acc[mi][ni].w);
            }
        }
    }
}

// ---------------- kernel 3: fused (partial-lse reduce) + (masked sim lse) + combine ----------------
__global__ void k_post() {
    __shared__ float rm[256], rs[256];
    __shared__ float posbuf[Ll];
    __shared__ float s_pos, s_lseq, s_lse;
    const int bid = blockIdx.x, tid = threadIdx.x;
    const bool is_g = (bid >= Nn);
    const int a = bid, gb = bid - Nn;

    // ---- phase A: lse over 1024 queue partials ----
    const float* p = d_part + bid * NT_Q;
    float vals[4];
    float m = -INFINITY;
#pragma unroll
    for (int i = 0; i < 4; i++) { vals[i] = p[tid + i * 256]; m = fmaxf(m, vals[i]); }
    rm[tid] = m; __syncthreads();
    for (int st = 128; st; st >>= 1) {
        if (tid < st) rm[tid] = fmaxf(rm[tid], rm[tid + st]);
        __syncthreads();
    }
    const float M = rm[0]; __syncthreads();
    float s = 0.f;
#pragma unroll
    for (int i = 0; i < 4; i++) s += __expf(vals[i] - M);
    rs[tid] = s; __syncthreads();
    for (int st = 128; st; st >>= 1) {
        if (tid < st) rs[tid] += rs[tid + st];
        __syncthreads();
    }
    if (tid == 0) s_lseq = M + __logf(rs[0]);
    __syncthreads();

    // ---- phase B: masked lse over the 512 precomputed sims ----
    float mm = -INFINITY, sacc = 0.f;
#pragma unroll
    for (int rep = 0; rep < 2; rep++) {
        const int j = tid + rep * 256;
        const float v = d_Sim[bid * Nn + j];
        bool masked = false;
        if (is_g) { if ((j >> 5) == gb) { posbuf[j & 31] = v; masked = true; } }
        else {
            if (j == a) masked = true;
            else if (j == a + 1) { s_pos = v; masked = true; }
        }
        if (!masked) {
            if (v > mm) { sacc = sacc * expf(mm - v) + 1.f; mm = v; }
            else        { sacc += expf(v - mm); }
        }
    }
    rm[tid] = mm; rs[tid] = sacc;
    __syncthreads();
    for (int st = 128; st; st >>= 1) {
        if (tid < st) {
            float m1 = rm[tid], s1 = rs[tid];
            float m2 = rm[tid + st], s2 = rs[tid + st];
            float nm = fmaxf(m1, m2);
            float ns = (nm == -INFINITY) ? 0.f : s1 * expf(m1 - nm) + s2 * expf(m2 - nm);
            rm[tid] = nm; rs[tid] = ns;
        }
        __syncthreads();
    }
    if (tid == 0) {
        const float lneg = rm[0] + logf(rs[0]);
        const float lq = s_lseq;
        const float hi = fmaxf(lneg, lq), lo = fminf(lneg, lq);
        s_lse = hi + log1pf(expf(lo - hi));
    }
    __syncthreads();
    if (!is_g) {
        const int t = a & (Ll - 1);
        if (t < Ll - 1 && tid == 0)
            d_llterms[(a >> 5) * (Ll - 1) + t] = softplusf(s_lse - s_pos);
    } else {
        if (tid < Ll) d_glterms[gb * Ll + tid] = softplusf(s_lse - posbuf[tid]);
    }
}

// ---------------- kernel 4: deterministic final reduction ----------------
__global__ void k_final(const float* __restrict__ z, float* __restrict__ out) {
    __shared__ float sm[256];
    const int tid = threadIdx.x;
    float sll = 0.f;
    for (int i = tid; i < MLL; i += 256) sll += d_llterms[i];
    float sgl = 0.f;
    for (int i = tid; i < Nn; i += 256) sgl += d_glterms[i];
    float ssm = 0.f;
    const int total = Bb * (Ll - 1) * Dd;
    for (int i = tid; i < total; i += 256) {
        int b = i / ((Ll - 1) * Dd);
        int r = i % ((Ll - 1) * Dd);
        int t = r >> 8, d = r & 255;
        float df = z[(b * Ll + t + 1) * Dd + d] - z[(b * Ll + t) * Dd + d];
        ssm += df * df;
    }
    float Sll, Sgl, Ssm;
    sm[tid] = sll; __syncthreads();
    for (int st = 128; st; st >>= 1) { if (tid < st) sm[tid] += sm[tid + st]; __syncthreads(); }
    Sll = sm[0]; __syncthreads();
    sm[tid] = sgl; __syncthreads();
    for (int st = 128; st; st >>= 1) { if (tid < st) sm[tid] += sm[tid + st]; __syncthreads(); }
    Sgl = sm[0]; __syncthreads();
    sm[tid] = ssm; __syncthreads();
    for (int st = 128; st; st >>= 1) { if (tid < st) sm[tid] += sm[tid + st]; __syncthreads(); }
    Ssm = sm[0];
    if (tid == 0)
        out[0] = Sll / (float)MLL + 0.5f * (Sgl / (float)Nn) + 0.1f * (Ssm / (float)MLL);
}

// ---------------- launch ----------------
extern "C" void kernel_launch(void* const* d_in, const int* in_sizes, int n_in,
                              void* d_out, int out_size) {
    const float* z  = (const float*)d_in[0];
    const float* g  = (const float*)d_in[1];
    const float* mq = (const float*)d_in[3];
    float* out = (float*)d_out;

    cudaFuncSetAttribute(k_gemm, cudaFuncAttributeMaxDynamicSharedMemorySize, SMEM_BYTES);

    k_prep<<<NQP, 256>>>(z, g);
    dim3 grid(MT, NT);     // mtile fastest -> 3 blocks sharing a key tile run together
    k_gemm<<<grid, 256, SMEM_BYTES>>>(mq, z);
    k_post<<<NQ, 256>>>();
    k_final<<<1, 256>>>(z, out);
}

// round 9
// speedup vs baseline: 2.0612x; 1.1300x over previous
#include <cuda_runtime.h>
#include <cuda_bf16.h>
#include <cstdint>
#include <math.h>

// ---------------- problem constants ----------------
#define INV_TAU (1.0f / 0.07f)
constexpr int Bb = 16, Ll = 32, Dd = 256, Kk = 131072;
constexpr int Nn = 512;          // B*L frames
constexpr int NQ = 528;          // 512 z rows + 16 g rows
constexpr int NQP = 576;         // padded to 3*192
constexpr int BM = 192, BN = 128, BK = 32;
constexpr int NT_Q = Kk / BN;    // 1024 queue tiles
constexpr int NT_Z = Nn / BN;    // 4 z-key tiles
constexpr int NT = NT_Q + NT_Z;  // 1028
constexpr int MT = NQP / BM;     // 3
constexpr int MLL = Bb * (Ll - 1);

// smem layout: A bf16 pitch 40 (80B rows), B fp32 pitch 40 (160B rows); 3 stages
constexpr int APB = 40;                       // A: bf16 elems per row slot
constexpr int A_BYTES = BM * APB * 2;         // 15360 per stage
constexpr int B_BYTES = BN * APB * 4;         // 20480 per stage (fp32)
constexpr int OFF_B = 3 * A_BYTES;            // 46080
constexpr int OFF_RED = OFF_B + 3 * B_BYTES;  // 107520
constexpr int SMEM_BYTES = OFF_RED + BM * 2 * 4 * 2;  // 110592

// ---------------- device scratch ----------------
__device__ __nv_bfloat16 d_Qbuf[NQP * Dd];    // scaled bf16 queries
__device__ float d_part[NQP * NT_Q];
__device__ float d_Sim[NQP * Nn];
__device__ float d_llterms[MLL];
__device__ float d_glterms[Nn];
__device__ float d_smterms[Nn];               // per-frame smoothness partials (496 used)

// ---------------- helpers ----------------
__device__ __forceinline__ void mma16(float4& d, const uint32_t* a, const uint32_t* b) {
    asm volatile(
        "mma.sync.aligned.m16n8k16.row.col.f32.bf16.bf16.f32 "
        "{%0,%1,%2,%3}, {%4,%5,%6,%7}, {%8,%9}, {%0,%1,%2,%3};\n"
        : "+f"(d.x), "+f"(d.y), "+f"(d.z), "+f"(d.w)
        : "r"(a[0]), "r"(a[1]), "r"(a[2]), "r"(a[3]), "r"(b[0]), "r"(b[1]));
}
__device__ __forceinline__ void cpasync16(uint32_t dst, const void* src) {
    asm volatile("cp.async.cg.shared.global [%0], [%1], 16;\n" :: "r"(dst), "l"(src));
}
__device__ __forceinline__ float softplusf(float x) {
    return (x > 0.f) ? x + log1pf(expf(-x)) : log1pf(expf(x));
}
__device__ __forceinline__ uint32_t bf2_bits(float lo, float hi) {
    __nv_bfloat162 p = __float22bfloat162_rn(make_float2(lo, hi));
    return *reinterpret_cast<uint32_t*>(&p);
}

// ---------------- kernel 1: queries (scaled) -> bf16 ----------------
__global__ void k_prep(const float* __restrict__ z, const float* __restrict__ g) {
    const int i = blockIdx.x * blockDim.x + threadIdx.x;   // 0 .. NQP*Dd-1
    const int row = i >> 8, d = i & 255;
    float v = 0.f;
    if (row < Nn)       v = z[i] * INV_TAU;
    else if (row < NQ)  v = g[(row - Nn) * Dd + d] * INV_TAU;
    d_Qbuf[i] = __float2bfloat16_rn(v);
}

// ---------------- kernel 2: 3-stage pipelined bf16 GEMM, fp32 keys in smem ----------------
__global__ __launch_bounds__(256, 1) void k_gemm(const float* __restrict__ mq,
                                                 const float* __restrict__ zk) {
    extern __shared__ char smc[];
    const uint32_t smem_u32 = (uint32_t)__cvta_generic_to_shared(smc);

    const int tid  = threadIdx.x;
    const int warp = tid >> 5, lane = tid & 31;
    const int wm = warp >> 1, wn = warp & 1;   // 4 x 2 warp grid
    const int g8 = lane >> 2, tg = lane & 3;
    const int mtile = blockIdx.x;
    const int ntile = blockIdx.y;
    const bool is_z = (ntile >= NT_Q);

    const __nv_bfloat16* Qb = d_Qbuf + mtile * BM * Dd;
    const float* Kb = is_z ? (zk + (size_t)(ntile - NT_Q) * BN * Dd)
                           : (mq + (size_t)ntile * BN * Dd);

    float4 acc[3][8];
#pragma unroll
    for (int mi = 0; mi < 3; mi++)
#pragma unroll
        for (int ni = 0; ni < 8; ni++) acc[mi][ni] = make_float4(0.f, 0.f, 0.f, 0.f);

    // A: 192x32 bf16 = 768 x16B (3/thread). B: 128x32 fp32 = 1024 x16B (4/thread).
#define LOAD_STAGE(s, kk)                                                            \
    do {                                                                             \
        _Pragma("unroll")                                                            \
        for (int i = 0; i < 3; i++) {                                                \
            int id = tid + i * 256; int r = id >> 2, c8 = id & 3;                    \
            uint32_t dst = smem_u32 + (s) * A_BYTES + (r * APB + c8 * 8) * 2;        \
            cpasync16(dst, Qb + r * Dd + (kk) * BK + c8 * 8);                        \
        }                                                                            \
        _Pragma("unroll")                                                            \
        for (int i = 0; i < 4; i++) {                                                \
            int id = tid + i * 256; int r = id >> 3, c4 = id & 7;                    \
            uint32_t dst = smem_u32 + OFF_B + (s) * B_BYTES + (r * APB + c4 * 4) * 4; \
            cpasync16(dst, Kb + r * Dd + (kk) * BK + c4 * 4);                        \
        }                                                                            \
    } while (0)

    LOAD_STAGE(0, 0);
    asm volatile("cp.async.commit_group;\n");
    LOAD_STAGE(1, 1);
    asm volatile("cp.async.commit_group;\n");

#pragma unroll 1
    for (int kk = 0; kk < 8; kk++) {
        asm volatile("cp.async.wait_group 1;\n");
        __syncthreads();
        const int s = kk - (kk >= 3 ? 3 : 0) - (kk >= 6 ? 3 : 0);   // kk % 3
        if (kk + 2 < 8) {
            const int s2 = (kk + 2) - ((kk + 2) >= 3 ? 3 : 0) - ((kk + 2) >= 6 ? 3 : 0);
            LOAD_STAGE(s2, kk + 2);
        }
        asm volatile("cp.async.commit_group;\n");

        const __nv_bfloat16* As = (const __nv_bfloat16*)(smc + s * A_BYTES);
        const float* Bs = (const float*)(smc + OFF_B + s * B_BYTES);

#pragma unroll
        for (int ks = 0; ks < 2; ks++) {
            const int k0 = ks * 16;
            uint32_t a[3][4];
#pragma unroll
            for (int mi = 0; mi < 3; mi++) {
                const int r0 = (wm * 48 + mi * 16 + g8) * APB;
                a[mi][0] = *(const uint32_t*)&As[r0 + k0 + tg * 2];
                a[mi][1] = *(const uint32_t*)&As[r0 + 8 * APB + k0 + tg * 2];
                a[mi][2] = *(const uint32_t*)&As[r0 + k0 + tg * 2 + 8];
                a[mi][3] = *(const uint32_t*)&As[r0 + 8 * APB + k0 + tg * 2 + 8];
            }
            uint32_t b[8][2];
#pragma unroll
            for (int ni = 0; ni < 8; ni++) {
                const float* bp = &Bs[(wn * 64 + ni * 8 + g8) * APB + k0 + tg * 2];
                float2 v0 = *(const float2*)bp;
                float2 v1 = *(const float2*)(bp + 8);
                b[ni][0] = bf2_bits(v0.x, v0.y);
                b[ni][1] = bf2_bits(v1.x, v1.y);
            }
#pragma unroll
            for (int mi = 0; mi < 3; mi++)
#pragma unroll
                for (int ni = 0; ni < 8; ni++) mma16(acc[mi][ni], a[mi], b[ni]);
        }
    }
#undef LOAD_STAGE

    if (!is_z) {
        // ---- per-row lse over this 128-col tile ----
        float* red_m = (float*)(smc + OFF_RED);
        float* red_s = red_m + BM * 2;
#pragma unroll
        for (int mi = 0; mi < 3; mi++) {
#pragma unroll
            for (int half = 0; half < 2; half++) {
                float v[16];
#pragma unroll
                for (int ni = 0; ni < 8; ni++) {
                    v[2 * ni]     = half ? acc[mi][ni].z : acc[mi][ni].x;
                    v[2 * ni + 1] = half ? acc[mi][ni].w : acc[mi][ni].y;
                }
                float m = v[0];
#pragma unroll
                for (int i = 1; i < 16; i++) m = fmaxf(m, v[i]);
                float s = 0.f;
#pragma unroll
                for (int i = 0; i < 16; i++) s += __expf(v[i] - m);
#pragma unroll
                for (int o = 1; o < 4; o <<= 1) {
                    float om = __shfl_xor_sync(0xffffffffu, m, o);
                    float os = __shfl_xor_sync(0xffffffffu, s, o);
                    float nm = fmaxf(m, om);
                    s = s * __expf(m - nm) + os * __expf(om - nm);
                    m = nm;
                }
                if (tg == 0) {
                    int rl = wm * 48 + mi * 16 + half * 8 + g8;
                    red_m[rl * 2 + wn] = m;
                    red_s[rl * 2 + wn] = s;
                }
            }
        }
        __syncthreads();
        if (tid < BM) {
            float m = red_m[tid * 2], s = red_s[tid * 2];
            float om = red_m[tid * 2 + 1], os = red_s[tid * 2 + 1];
            float nm = fmaxf(m, om);
            s = s * __expf(m - nm) + os * __expf(om - nm);
            int grow = mtile * BM + tid;
            if (grow < NQ) d_part[grow * NT_Q + ntile] = nm + __logf(s);
        }
    } else {
        // ---- write raw sims for the z-key tiles ----
        const int col0 = (ntile - NT_Q) * BN + wn * 64;
#pragma unroll
        for (int mi = 0; mi < 3; mi++) {
            const int row0 = mtile * BM + wm * 48 + mi * 16 + g8;
#pragma unroll
            for (int ni = 0; ni < 8; ni++) {
                const int c = col0 + ni * 8 + 2 * tg;
                *(float2*)&d_Sim[row0 * Nn + c]       = make_float2(acc[mi][ni].x, acc[mi][ni].y);
                *(float2*)&d_Sim[(row0 + 8) * Nn + c] = make_float2(acc[mi][ni].z, acc[mi][ni].w);
            }
        }
    }
}

// ---------------- kernel 3: fused reduce + masked lse + combine + smoothness ----------------
__global__ void k_post(const float* __restrict__ z) {
    __shared__ float rm[256], rs[256];
    __shared__ float posbuf[Ll];
    __shared__ float s_pos, s_lseq, s_lse;
    const int bid = blockIdx.x, tid = threadIdx.x;
    const bool is_g = (bid >= Nn);
    const int a = bid, gb = bid - Nn;

    // ---- phase A: lse over 1024 queue partials ----
    const float* p = d_part + bid * NT_Q;
    float vals[4];
    float m = -INFINITY;
#pragma unroll
    for (int i = 0; i < 4; i++) { vals[i] = p[tid + i * 256]; m = fmaxf(m, vals[i]); }
    rm[tid] = m; __syncthreads();
    for (int st = 128; st; st >>= 1) {
        if (tid < st) rm[tid] = fmaxf(rm[tid], rm[tid + st]);
        __syncthreads();
    }
    const float M = rm[0]; __syncthreads();
    float s = 0.f;
#pragma unroll
    for (int i = 0; i < 4; i++) s += __expf(vals[i] - M);
    rs[tid] = s; __syncthreads();
    for (int st = 128; st; st >>= 1) {
        if (tid < st) rs[tid] += rs[tid + st];
        __syncthreads();
    }
    if (tid == 0) s_lseq = M + __logf(rs[0]);
    __syncthreads();

    // ---- phase B: masked lse over the 512 precomputed sims ----
    float mm = -INFINITY, sacc = 0.f;
#pragma unroll
    for (int rep = 0; rep < 2; rep++) {
        const int j = tid + rep * 256;
        const float v = d_Sim[bid * Nn + j];
        bool masked = false;
        if (is_g) { if ((j >> 5) == gb) { posbuf[j & 31] = v; masked = true; } }
        else {
            if (j == a) masked = true;
            else if (j == a + 1) { s_pos = v; masked = true; }
        }
        if (!masked) {
            if (v > mm) { sacc = sacc * expf(mm - v) + 1.f; mm = v; }
            else        { sacc += expf(v - mm); }
        }
    }
    rm[tid] = mm; rs[tid] = sacc;
    __syncthreads();
    for (int st = 128; st; st >>= 1) {
        if (tid < st) {
            float m1 = rm[tid], s1 = rs[tid];
            float m2 = rm[tid + st], s2 = rs[tid + st];
            float nm = fmaxf(m1, m2);
            float ns = (nm == -INFINITY) ? 0.f : s1 * expf(m1 - nm) + s2 * expf(m2 - nm);
            rm[tid] = nm; rs[tid] = ns;
        }
        __syncthreads();
    }
    if (tid == 0) {
        const float lneg = rm[0] + logf(rs[0]);
        const float lq = s_lseq;
        const float hi = fmaxf(lneg, lq), lo = fminf(lneg, lq);
        s_lse = hi + log1pf(expf(lo - hi));
    }
    __syncthreads();
    if (!is_g) {
        const int t = a & (Ll - 1);
        if (t < Ll - 1 && tid == 0)
            d_llterms[(a >> 5) * (Ll - 1) + t] = softplusf(s_lse - s_pos);
    } else {
        if (tid < Ll) d_glterms[gb * Ll + tid] = softplusf(s_lse - posbuf[tid]);
    }

    // ---- phase C: per-frame smoothness partial (z blocks with t < Ll-1) ----
    if (!is_g && (a & (Ll - 1)) < Ll - 1) {
        const float df = z[(a + 1) * Dd + tid] - z[a * Dd + tid];
        __syncthreads();
        rm[tid] = df * df;
        __syncthreads();
        for (int st = 128; st; st >>= 1) {
            if (tid < st) rm[tid] += rm[tid + st];
            __syncthreads();
        }
        if (tid == 0) {
            const int t = a & (Ll - 1);
            d_smterms[(a >> 5) * (Ll - 1) + t] = rm[0];
        }
    }
}

// ---------------- kernel 4: tiny deterministic final combine ----------------
__global__ void k_final(float* __restrict__ out) {
    __shared__ float sm[256];
    const int tid = threadIdx.x;
    float sll = 0.f, sgl = 0.f, ssm = 0.f;
    for (int i = tid; i < MLL; i += 256) { sll += d_llterms[i]; ssm += d_smterms[i]; }
    for (int i = tid; i < Nn; i += 256) sgl += d_glterms[i];

    float Sll, Sgl, Ssm;
    sm[tid] = sll; __syncthreads();
    for (int st = 128; st; st >>= 1) { if (tid < st) sm[tid] += sm[tid + st]; __syncthreads(); }
    Sll = sm[0]; __syncthreads();
    sm[tid] = sgl; __syncthreads();
    for (int st = 128; st; st >>= 1) { if (tid < st) sm[tid] += sm[tid + st]; __syncthreads(); }
    Sgl = sm[0]; __syncthreads();
    sm[tid] = ssm; __syncthreads();
    for (int st = 128; st; st >>= 1) { if (tid < st) sm[tid] += sm[tid + st]; __syncthreads(); }
    Ssm = sm[0];
    if (tid == 0)
        out[0] = Sll / (float)MLL + 0.5f * (Sgl / (float)Nn) + 0.1f * (Ssm / (float)MLL);
}

// ---------------- launch ----------------
extern "C" void kernel_launch(void* const* d_in, const int* in_sizes, int n_in,
                              void* d_out, int out_size) {
    const float* z  = (const float*)d_in[0];
    const float* g  = (const float*)d_in[1];
    const float* mq = (const float*)d_in[3];
    float* out = (float*)d_out;

    cudaFuncSetAttribute(k_gemm, cudaFuncAttributeMaxDynamicSharedMemorySize, SMEM_BYTES);

    k_prep<<<NQP, 256>>>(z, g);
    dim3 grid(MT, NT);     // mtile fastest -> 3 blocks sharing a key tile run together
    k_gemm<<<grid, 256, SMEM_BYTES>>>(mq, z);
    k_post<<<NQ, 256>>>(z);
    k_final<<<1, 256>>>(out);
}